// round 11
// baseline (speedup 1.0000x reference)
#include <cuda_runtime.h>
#include <cuda_fp16.h>
#include <math.h>
#include <stdint.h>

#define BS_  2
#define SEQ  2048
#define DIM  1024
#define NH   16
#define DFF  4096
#define MROWS (BS_*SEQ)   // 4096

// ---------------- Scratch ------------------------------------------------------
__device__ __half g_x  [MROWS * DIM];
__device__ __half g_qkv[MROWS * 3 * DIM];
__device__ __half g_att[MROWS * DIM];
__device__ float  g_h  [MROWS * DIM];
__device__ __half g_y  [MROWS * DIM];
__device__ __half g_fc [MROWS * DFF];
__device__ __half g_waT [3 * DIM * DIM];
__device__ __half g_wpT [DIM * DIM];
__device__ __half g_wfT [DFF * DIM];
__device__ __half g_wfpT[DIM * DFF];

// ---------------- helpers ------------------------------------------------------
__device__ __forceinline__ void mma16(float d[4], const uint32_t a[4],
                                      uint32_t b0, uint32_t b1) {
    asm volatile("mma.sync.aligned.m16n8k16.row.col.f32.f16.f16.f32 "
        "{%0,%1,%2,%3}, {%4,%5,%6,%7}, {%8,%9}, {%0,%1,%2,%3};\n"
        : "+f"(d[0]), "+f"(d[1]), "+f"(d[2]), "+f"(d[3])
        : "r"(a[0]), "r"(a[1]), "r"(a[2]), "r"(a[3]), "r"(b0), "r"(b1));
}
__device__ __forceinline__ void ldsm4(uint32_t r[4], uint32_t addr) {
    asm volatile("ldmatrix.sync.aligned.m8n8.x4.shared.b16 {%0,%1,%2,%3}, [%4];"
        : "=r"(r[0]), "=r"(r[1]), "=r"(r[2]), "=r"(r[3]) : "r"(addr));
}
__device__ __forceinline__ float gelu_f(float x) {
    float x3 = x * x * x;
    return 0.5f * x * (1.0f + tanhf(0.7978845608028654f * (x + 0.044715f * x3)));
}
__device__ __forceinline__ uint32_t smem_u32(const void* p) {
    uint32_t a;
    asm("{ .reg .u64 t; cvta.to.shared.u64 t, %1; cvt.u32.u64 %0, t; }" : "=r"(a) : "l"(p));
    return a;
}
__device__ __forceinline__ void cpa16(uint32_t dst, const void* src) {
    asm volatile("cp.async.cg.shared.global [%0], [%1], 16;" :: "r"(dst), "l"(src));
}
__device__ __forceinline__ uint32_t packh2(float a, float b) {
    __half2 h = __floats2half2_rn(a, b);
    return *(uint32_t*)&h;
}
__device__ __forceinline__ void storeC(float* C, size_t idx, float v0, float v1) {
    *(float2*)&C[idx] = make_float2(v0, v1);
}
__device__ __forceinline__ void storeC(__half* C, size_t idx, float v0, float v1) {
    *(__half2*)&C[idx] = __floats2half2_rn(v0, v1);
}

// ---------------- weight convert + transpose (half2 stores) --------------------
// in: [K,N] fp32 -> out: [N,K] fp16. 64k x 32n tile per block.
__global__ void __launch_bounds__(256)
wconv_t(const float* __restrict__ in, __half* __restrict__ out, int K, int N)
{
    __shared__ float tl[64][33];
    const int tx = threadIdx.x, ty = threadIdx.y;
    const int n0 = blockIdx.x * 32, k0 = blockIdx.y * 64;
    #pragma unroll
    for (int j = 0; j < 8; j++) {
        int kr = ty + 8 * j;
        tl[kr][tx] = in[(size_t)(k0 + kr) * N + n0 + tx];
    }
    __syncthreads();
    #pragma unroll
    for (int j = 0; j < 4; j++) {
        int n = ty + 8 * j;
        __half2 h = __floats2half2_rn(tl[2 * tx][n], tl[2 * tx + 1][n]);
        *(__half2*)&out[(size_t)(n0 + n) * K + k0 + 2 * tx] = h;
    }
}

// ---------------- LayerNorm (fp32 in, fp16 out) --------------------------------
__global__ void __launch_bounds__(256)
ln_h(const float* __restrict__ in, const float* __restrict__ w,
     const float* __restrict__ b, __half* __restrict__ out)
{
    int row = blockIdx.x;
    int t = threadIdx.x;
    const float4* ip = (const float4*)(in + (size_t)row * DIM);
    float4 x = ip[t];
    float s  = x.x + x.y + x.z + x.w;
    float ss = x.x*x.x + x.y*x.y + x.z*x.z + x.w*x.w;
    #pragma unroll
    for (int off = 16; off; off >>= 1) {
        s  += __shfl_xor_sync(0xFFFFFFFFu, s,  off);
        ss += __shfl_xor_sync(0xFFFFFFFFu, ss, off);
    }
    __shared__ float sh_s[8], sh_ss[8];
    int wid = t >> 5, lid = t & 31;
    if (lid == 0) { sh_s[wid] = s; sh_ss[wid] = ss; }
    __syncthreads();
    float S = 0.f, SS = 0.f;
    #pragma unroll
    for (int i = 0; i < 8; i++) { S += sh_s[i]; SS += sh_ss[i]; }
    float mean = S * (1.0f / DIM);
    float var  = SS * (1.0f / DIM) - mean * mean;
    float inv  = rsqrtf(var + 1e-6f);
    float4 wv = ((const float4*)w)[t];
    float4 bv = ((const float4*)b)[t];
    __half2* op = (__half2*)(out + (size_t)row * DIM + 4 * t);
    op[0] = __floats2half2_rn((x.x - mean) * inv * wv.x + bv.x,
                              (x.y - mean) * inv * wv.y + bv.y);
    op[1] = __floats2half2_rn((x.z - mean) * inv * wv.z + bv.z,
                              (x.w - mean) * inv * wv.w + bv.w);
}

// ---------------- FP16 GEMM: 128x256 CTA tile, 512 thr, warp tile 64x32 --------
#define HSTRIDE 72
#define A_HALFS (128 * HSTRIDE)      // 9216
#define B_HALFS (256 * HSTRIDE)      // 18432
#define STGH (A_HALFS + B_HALFS)     // 27648 halfs
#define STB (STGH * 2)               // 55296 B per stage
#define NST 3
#define GEMM_SMEM (NST * STB)        // 165888 B

template<int EPI, typename OutT>
__global__ void __launch_bounds__(512, 1)
gemm_h(const __half* __restrict__ A, const __half* __restrict__ Bt,
       const float* __restrict__ bias, const float* __restrict__ res,
       OutT* __restrict__ C, int M, int N, int K)
{
    extern __shared__ __half smh[];
    const uint32_t sb = smem_u32(smh);

    const int t = threadIdx.x;
    const int lane = t & 31, w = t >> 5;
    const int wr = w >> 3, wc = w & 7;             // 2 x 8 warp grid
    const int g = lane >> 2, c = lane & 3;
    const int row0 = blockIdx.y * 128, col0 = blockIdx.x * 256;
    const int nk = K / 64;

    // ldmatrix per-lane source mapping
    const int a_r = (lane & 7) + ((lane >> 3) & 1) * 8;
    const int a_c = (lane >> 4) * 8;
    const int b_n = (lane & 7) + (lane >> 4) * 8;
    const int b_k = ((lane >> 3) & 1) * 8;

    // producers: A 2 chunks/thread (128 rows x 8 chunks), B 4 chunks/thread (256 x 8)
    uint32_t aDst[2]; const __half* aSrc[2];
    #pragma unroll
    for (int j = 0; j < 2; j++) {
        int cid = t + 512 * j;
        int r = cid >> 3, ch = cid & 7;
        aDst[j] = sb + r * (HSTRIDE * 2) + ch * 16;
        aSrc[j] = A + (size_t)(row0 + r) * K + ch * 8;
    }
    uint32_t bDst[4]; const __half* bSrc[4];
    #pragma unroll
    for (int j = 0; j < 4; j++) {
        int cid = t + 512 * j;
        int r = cid >> 3, ch = cid & 7;
        bDst[j] = sb + A_HALFS * 2 + r * (HSTRIDE * 2) + ch * 16;
        bSrc[j] = Bt + (size_t)(col0 + r) * K + ch * 8;
    }

    float acc[4][4][4];
    #pragma unroll
    for (int i = 0; i < 4; i++)
        #pragma unroll
        for (int j = 0; j < 4; j++)
            #pragma unroll
            for (int q = 0; q < 4; q++) acc[i][j][q] = 0.f;

    #pragma unroll
    for (int pt = 0; pt < 2; pt++) {
        #pragma unroll
        for (int j = 0; j < 2; j++) cpa16(aDst[j] + pt * STB, aSrc[j] + pt * 64);
        #pragma unroll
        for (int j = 0; j < 4; j++) cpa16(bDst[j] + pt * STB, bSrc[j] + pt * 64);
        asm volatile("cp.async.commit_group;");
    }

    int s = 0;
    #pragma unroll 1
    for (int kt = 0; kt < nk; kt++) {
        asm volatile("cp.async.wait_group 1;");
        __syncthreads();

        const uint32_t AbU = sb + s * STB;
        const uint32_t BbU = AbU + A_HALFS * 2;
        const uint32_t aBase = AbU + ((wr * 64 + a_r) * HSTRIDE + a_c) * 2;
        const uint32_t bBase = BbU + ((wc * 32 + b_n) * HSTRIDE + b_k) * 2;

        #pragma unroll
        for (int kk = 0; kk < 4; kk++) {
            uint32_t af[4][4], bf[2][4];
            #pragma unroll
            for (int mt = 0; mt < 4; mt++)
                ldsm4(af[mt], aBase + mt * 16 * (HSTRIDE * 2) + kk * 32);
            #pragma unroll
            for (int nt2 = 0; nt2 < 2; nt2++)
                ldsm4(bf[nt2], bBase + nt2 * 16 * (HSTRIDE * 2) + kk * 32);
            #pragma unroll
            for (int mt = 0; mt < 4; mt++)
                #pragma unroll
                for (int nt = 0; nt < 4; nt++)
                    mma16(acc[mt][nt], af[mt],
                          bf[nt >> 1][(nt & 1) * 2], bf[nt >> 1][(nt & 1) * 2 + 1]);
        }

        if (kt + 2 < nk) {
            const int sp = (s + 2) % NST;
            const int kg = (kt + 2) * 64;
            #pragma unroll
            for (int j = 0; j < 2; j++) cpa16(aDst[j] + sp * STB, aSrc[j] + kg);
            #pragma unroll
            for (int j = 0; j < 4; j++) cpa16(bDst[j] + sp * STB, bSrc[j] + kg);
        }
        asm volatile("cp.async.commit_group;");

        if (++s == NST) s = 0;
    }

    // epilogue
    #pragma unroll
    for (int mt = 0; mt < 4; mt++) {
        int r1 = row0 + wr * 64 + mt * 16 + g;
        int r2 = r1 + 8;
        #pragma unroll
        for (int nt = 0; nt < 4; nt++) {
            int col = col0 + wc * 32 + nt * 8 + 2 * c;
            float2 bv = *(const float2*)&bias[col];
            float v0 = acc[mt][nt][0] + bv.x;
            float v1 = acc[mt][nt][1] + bv.y;
            float v2 = acc[mt][nt][2] + bv.x;
            float v3 = acc[mt][nt][3] + bv.y;
            if (EPI == 1) {
                v0 = gelu_f(v0); v1 = gelu_f(v1); v2 = gelu_f(v2); v3 = gelu_f(v3);
            } else if (EPI == 2) {
                float2 ra = *(const float2*)&res[(size_t)r1 * N + col];
                float2 rb = *(const float2*)&res[(size_t)r2 * N + col];
                v0 += ra.x; v1 += ra.y; v2 += rb.x; v3 += rb.y;
            }
            storeC(C, (size_t)r1 * N + col, v0, v1);
            storeC(C, (size_t)r2 * N + col, v2, v3);
        }
    }
}

// ---------------- Flash attention: ldmatrix K, double-buffered K/V (R10) -------
#define KVB (64 * HSTRIDE * 2)

__global__ void __launch_bounds__(256)
attn_h(const __half* __restrict__ qkv, __half* __restrict__ out)
{
    __shared__ __half ks[2][64][HSTRIDE];
    __shared__ __half vs[2][64][HSTRIDE];

    const int t = threadIdx.x, lane = t & 31, w = t >> 5;
    const int g = lane >> 2, c = lane & 3;
    const int bq = blockIdx.x * 128;
    const int b = blockIdx.y >> 4, h = blockIdx.y & 15;
    const int qg0 = bq + w * 16 + g;

    const uint32_t ksb = smem_u32(&ks[0][0][0]);
    const uint32_t vsb = smem_u32(&vs[0][0][0]);

    const int b_n = (lane & 7) + (lane >> 4) * 8;
    const int b_k = ((lane >> 3) & 1) * 8;
    const int lm_r = ((lane >> 3) & 1) * 8 + (lane & 7);
    const int lm_jofs = (lane >> 4);

    uint32_t aq[4][4];
    {
        const __half* q0p = qkv + ((size_t)(b * SEQ + qg0)) * (3 * DIM) + h * 64;
        const __half* q1p = q0p + (size_t)8 * (3 * DIM);
        const __half2 sc = __half2half2(__float2half(0.125f));
        #pragma unroll
        for (int kk = 0; kk < 4; kk++) {
            __half2 v0 = __hmul2(*(const __half2*)(q0p + kk * 16 + 2 * c), sc);
            __half2 v1 = __hmul2(*(const __half2*)(q1p + kk * 16 + 2 * c), sc);
            __half2 v2 = __hmul2(*(const __half2*)(q0p + kk * 16 + 2 * c + 8), sc);
            __half2 v3 = __hmul2(*(const __half2*)(q1p + kk * 16 + 2 * c + 8), sc);
            aq[kk][0] = *(uint32_t*)&v0; aq[kk][1] = *(uint32_t*)&v1;
            aq[kk][2] = *(uint32_t*)&v2; aq[kk][3] = *(uint32_t*)&v3;
        }
    }

    float o[8][4];
    #pragma unroll
    for (int i = 0; i < 8; i++) { o[i][0] = o[i][1] = o[i][2] = o[i][3] = 0.f; }
    float m0 = -1e30f, m1 = -1e30f, l0 = 0.f, l1 = 0.f;

    const int lrow0 = t >> 3, lch = t & 7;
    const int kend = blockIdx.x * 2 + 1;

    {
        #pragma unroll
        for (int j = 0; j < 2; j++) {
            int row = lrow0 + 32 * j;
            const __half* kp = qkv + ((size_t)(b * SEQ + row)) * (3 * DIM)
                               + DIM + h * 64 + lch * 8;
            cpa16(ksb + row * (HSTRIDE * 2) + lch * 16, kp);
            cpa16(vsb + row * (HSTRIDE * 2) + lch * 16, kp + DIM);
        }
        asm volatile("cp.async.commit_group;");
    }

    #pragma unroll 1
    for (int kt = 0; kt <= kend; kt++) {
        const int bi = kt & 1;
        if (kt < kend) {
            const int ni = (kt + 1) & 1;
            #pragma unroll
            for (int j = 0; j < 2; j++) {
                int row = lrow0 + 32 * j;
                const __half* kp = qkv + ((size_t)(b * SEQ + (kt + 1) * 64 + row)) * (3 * DIM)
                                   + DIM + h * 64 + lch * 8;
                cpa16(ksb + ni * KVB + row * (HSTRIDE * 2) + lch * 16, kp);
                cpa16(vsb + ni * KVB + row * (HSTRIDE * 2) + lch * 16, kp + DIM);
            }
        }
        asm volatile("cp.async.commit_group; cp.async.wait_group 1;");
        __syncthreads();

        float sacc[8][4];
        #pragma unroll
        for (int i = 0; i < 8; i++) { sacc[i][0] = sacc[i][1] = sacc[i][2] = sacc[i][3] = 0.f; }
        const uint32_t kBase = ksb + bi * KVB + (b_n * HSTRIDE + b_k) * 2;
        #pragma unroll
        for (int kk = 0; kk < 4; kk++) {
            uint32_t kf[4][4];
            #pragma unroll
            for (int nt2 = 0; nt2 < 4; nt2++)
                ldsm4(kf[nt2], kBase + nt2 * 16 * (HSTRIDE * 2) + kk * 32);
            #pragma unroll
            for (int nt = 0; nt < 8; nt++)
                mma16(sacc[nt], aq[kk],
                      kf[nt >> 1][(nt & 1) * 2], kf[nt >> 1][(nt & 1) * 2 + 1]);
        }

        if (kt * 64 + 63 > bq + w * 16) {
            #pragma unroll
            for (int nt = 0; nt < 8; nt++) {
                int colb = kt * 64 + nt * 8 + 2 * c;
                if (colb     > qg0)     sacc[nt][0] = -1e30f;
                if (colb + 1 > qg0)     sacc[nt][1] = -1e30f;
                if (colb     > qg0 + 8) sacc[nt][2] = -1e30f;
                if (colb + 1 > qg0 + 8) sacc[nt][3] = -1e30f;
            }
        }

        float mx0 = -1e30f, mx1 = -1e30f;
        #pragma unroll
        for (int nt = 0; nt < 8; nt++) {
            mx0 = fmaxf(mx0, fmaxf(sacc[nt][0], sacc[nt][1]));
            mx1 = fmaxf(mx1, fmaxf(sacc[nt][2], sacc[nt][3]));
        }
        mx0 = fmaxf(mx0, __shfl_xor_sync(0xFFFFFFFFu, mx0, 1));
        mx0 = fmaxf(mx0, __shfl_xor_sync(0xFFFFFFFFu, mx0, 2));
        mx1 = fmaxf(mx1, __shfl_xor_sync(0xFFFFFFFFu, mx1, 1));
        mx1 = fmaxf(mx1, __shfl_xor_sync(0xFFFFFFFFu, mx1, 2));
        float nm0 = fmaxf(m0, mx0), nm1 = fmaxf(m1, mx1);
        float al0 = __expf(m0 - nm0), al1 = __expf(m1 - nm1);
        m0 = nm0; m1 = nm1;

        float ls0 = 0.f, ls1 = 0.f;
        uint32_t pa[4][4];
        #pragma unroll
        for (int nt = 0; nt < 8; nt++) {
            float p0 = __expf(sacc[nt][0] - nm0);
            float p1 = __expf(sacc[nt][1] - nm0);
            float p2 = __expf(sacc[nt][2] - nm1);
            float p3 = __expf(sacc[nt][3] - nm1);
            ls0 += p0 + p1; ls1 += p2 + p3;
            const int kk = nt >> 1;
            if ((nt & 1) == 0) {
                pa[kk][0] = packh2(p0, p1);
                pa[kk][1] = packh2(p2, p3);
            } else {
                pa[kk][2] = packh2(p0, p1);
                pa[kk][3] = packh2(p2, p3);
            }
            o[nt][0] *= al0; o[nt][1] *= al0;
            o[nt][2] *= al1; o[nt][3] *= al1;
        }
        ls0 += __shfl_xor_sync(0xFFFFFFFFu, ls0, 1);
        ls0 += __shfl_xor_sync(0xFFFFFFFFu, ls0, 2);
        ls1 += __shfl_xor_sync(0xFFFFFFFFu, ls1, 1);
        ls1 += __shfl_xor_sync(0xFFFFFFFFu, ls1, 2);
        l0 = l0 * al0 + ls0;
        l1 = l1 * al1 + ls1;

        const uint32_t vBase = vsb + bi * KVB;
        #pragma unroll
        for (int kk = 0; kk < 4; kk++) {
            #pragma unroll
            for (int j = 0; j < 8; j += 2) {
                uint32_t r0, r1, r2, r3;
                uint32_t addr = vBase + (kk * 16 + lm_r) * (HSTRIDE * 2)
                              + (j + lm_jofs) * 8 * 2;
                asm volatile(
                    "ldmatrix.sync.aligned.m8n8.x4.trans.shared.b16 {%0,%1,%2,%3}, [%4];"
                    : "=r"(r0), "=r"(r1), "=r"(r2), "=r"(r3) : "r"(addr));
                mma16(o[j],     pa[kk], r0, r1);
                mma16(o[j + 1], pa[kk], r2, r3);
            }
        }
        __syncthreads();
    }

    float il0 = 1.0f / l0, il1 = 1.0f / l1;
    size_t o0 = ((size_t)(b * SEQ + qg0)) * DIM + h * 64;
    size_t o1 = o0 + (size_t)8 * DIM;
    #pragma unroll
    for (int nt = 0; nt < 8; nt++) {
        int cl = nt * 8 + 2 * c;
        *(__half2*)&out[o0 + cl] = __floats2half2_rn(o[nt][0] * il0, o[nt][1] * il0);
        *(__half2*)&out[o1 + cl] = __floats2half2_rn(o[nt][2] * il1, o[nt][3] * il1);
    }
}

// ---------------- Launch -------------------------------------------------------
extern "C" void kernel_launch(void* const* d_in, const int* in_sizes, int n_in,
                              void* d_out, int out_size)
{
    const float* hidden    = (const float*)d_in[0];
    const float* w_attn    = (const float*)d_in[1];
    const float* b_attn    = (const float*)d_in[2];
    const float* w_proj    = (const float*)d_in[3];
    const float* b_proj    = (const float*)d_in[4];
    const float* w_fc      = (const float*)d_in[5];
    const float* b_fc      = (const float*)d_in[6];
    const float* w_fc_proj = (const float*)d_in[7];
    const float* b_fc_proj = (const float*)d_in[8];
    const float* ln1_w     = (const float*)d_in[9];
    const float* ln1_b     = (const float*)d_in[10];
    const float* ln2_w     = (const float*)d_in[11];
    const float* ln2_b     = (const float*)d_in[12];
    float* outp            = (float*)d_out;

    __half *px, *pqkv, *patt, *py, *pfc, *pwa, *pwp, *pwf, *pwfp;
    float *ph;
    cudaGetSymbolAddress((void**)&px,   g_x);
    cudaGetSymbolAddress((void**)&pqkv, g_qkv);
    cudaGetSymbolAddress((void**)&patt, g_att);
    cudaGetSymbolAddress((void**)&ph,   g_h);
    cudaGetSymbolAddress((void**)&py,   g_y);
    cudaGetSymbolAddress((void**)&pfc,  g_fc);
    cudaGetSymbolAddress((void**)&pwa,  g_waT);
    cudaGetSymbolAddress((void**)&pwp,  g_wpT);
    cudaGetSymbolAddress((void**)&pwf,  g_wfT);
    cudaGetSymbolAddress((void**)&pwfp, g_wfpT);

    cudaFuncSetAttribute(gemm_h<0, __half>, cudaFuncAttributeMaxDynamicSharedMemorySize, GEMM_SMEM);
    cudaFuncSetAttribute(gemm_h<1, __half>, cudaFuncAttributeMaxDynamicSharedMemorySize, GEMM_SMEM);
    cudaFuncSetAttribute(gemm_h<2, float>,  cudaFuncAttributeMaxDynamicSharedMemorySize, GEMM_SMEM);

    // weight convert+transpose (half2 stores): in [K,N] -> out [N,K]
    wconv_t<<<dim3(3 * DIM / 32, DIM / 64), dim3(32, 8)>>>(w_attn,    pwa,  DIM, 3 * DIM);
    wconv_t<<<dim3(DIM / 32,     DIM / 64), dim3(32, 8)>>>(w_proj,    pwp,  DIM, DIM);
    wconv_t<<<dim3(DFF / 32,     DIM / 64), dim3(32, 8)>>>(w_fc,      pwf,  DIM, DFF);
    wconv_t<<<dim3(DIM / 32,     DFF / 64), dim3(32, 8)>>>(w_fc_proj, pwfp, DFF, DIM);

    ln_h<<<MROWS, 256>>>(hidden, ln1_w, ln1_b, px);

    gemm_h<0, __half><<<dim3(3 * DIM / 256, MROWS / 128), 512, GEMM_SMEM>>>(
        px, pwa, b_attn, nullptr, pqkv, MROWS, 3 * DIM, DIM);

    attn_h<<<dim3(SEQ / 128, BS_ * NH), 256>>>(pqkv, patt);

    gemm_h<2, float><<<dim3(DIM / 256, MROWS / 128), 512, GEMM_SMEM>>>(
        patt, pwp, b_proj, hidden, ph, MROWS, DIM, DIM);

    ln_h<<<MROWS, 256>>>(ph, ln2_w, ln2_b, py);

    gemm_h<1, __half><<<dim3(DFF / 256, MROWS / 128), 512, GEMM_SMEM>>>(
        py, pwf, b_fc, nullptr, pfc, MROWS, DFF, DIM);

    gemm_h<2, float><<<dim3(DIM / 256, MROWS / 128), 512, GEMM_SMEM>>>(
        pfc, pwfp, b_fc_proj, ph, outp, MROWS, DIM, DFF);
}

// round 15
// speedup vs baseline: 1.0668x; 1.0668x over previous
#include <cuda_runtime.h>
#include <cuda_fp16.h>
#include <math.h>
#include <stdint.h>

#define BS_  2
#define SEQ  2048
#define DIM  1024
#define NH   16
#define DFF  4096
#define MROWS (BS_*SEQ)   // 4096

// ---------------- Scratch ------------------------------------------------------
__device__ __half g_x  [MROWS * DIM];
__device__ __half g_qkv[MROWS * 3 * DIM];
__device__ __half g_att[MROWS * DIM];
__device__ float  g_h  [MROWS * DIM];
__device__ __half g_y  [MROWS * DIM];
__device__ __half g_fc [MROWS * DFF];
__device__ __half g_waT [3 * DIM * DIM];   // [N,K] fp16
__device__ __half g_wpT [DIM * DIM];
__device__ __half g_wfT [DFF * DIM];
__device__ __half g_wfpT[DIM * DFF];

// ---------------- helpers ------------------------------------------------------
__device__ __forceinline__ void mma16(float d[4], const uint32_t a[4],
                                      uint32_t b0, uint32_t b1) {
    asm volatile("mma.sync.aligned.m16n8k16.row.col.f32.f16.f16.f32 "
        "{%0,%1,%2,%3}, {%4,%5,%6,%7}, {%8,%9}, {%0,%1,%2,%3};\n"
        : "+f"(d[0]), "+f"(d[1]), "+f"(d[2]), "+f"(d[3])
        : "r"(a[0]), "r"(a[1]), "r"(a[2]), "r"(a[3]), "r"(b0), "r"(b1));
}
__device__ __forceinline__ void ldsm4(uint32_t r[4], uint32_t addr) {
    asm volatile("ldmatrix.sync.aligned.m8n8.x4.shared.b16 {%0,%1,%2,%3}, [%4];"
        : "=r"(r[0]), "=r"(r[1]), "=r"(r[2]), "=r"(r[3]) : "r"(addr));
}
__device__ __forceinline__ float gelu_f(float x) {
    float x3 = x * x * x;
    return 0.5f * x * (1.0f + tanhf(0.7978845608028654f * (x + 0.044715f * x3)));
}
__device__ __forceinline__ uint32_t smem_u32(const void* p) {
    uint32_t a;
    asm("{ .reg .u64 t; cvta.to.shared.u64 t, %1; cvt.u32.u64 %0, t; }" : "=r"(a) : "l"(p));
    return a;
}
__device__ __forceinline__ void cpa16(uint32_t dst, const void* src) {
    asm volatile("cp.async.cg.shared.global [%0], [%1], 16;" :: "r"(dst), "l"(src));
}
__device__ __forceinline__ uint32_t packh2(float a, float b) {
    __half2 h = __floats2half2_rn(a, b);
    return *(uint32_t*)&h;
}
__device__ __forceinline__ void storeC(float* C, size_t idx, float v0, float v1) {
    *(float2*)&C[idx] = make_float2(v0, v1);
}
__device__ __forceinline__ void storeC(__half* C, size_t idx, float v0, float v1) {
    *(__half2*)&C[idx] = __floats2half2_rn(v0, v1);
}

// ---------------- weight convert + transpose (half2 stores, R11 version) -------
// in: [K,N] fp32 -> out: [N,K] fp16. 64k x 32n tile per block.
__global__ void __launch_bounds__(256)
wconv_t(const float* __restrict__ in, __half* __restrict__ out, int K, int N)
{
    __shared__ float tl[64][33];
    const int tx = threadIdx.x, ty = threadIdx.y;
    const int n0 = blockIdx.x * 32, k0 = blockIdx.y * 64;
    #pragma unroll
    for (int j = 0; j < 8; j++) {
        int kr = ty + 8 * j;
        tl[kr][tx] = in[(size_t)(k0 + kr) * N + n0 + tx];
    }
    __syncthreads();
    #pragma unroll
    for (int j = 0; j < 4; j++) {
        int n = ty + 8 * j;
        __half2 h = __floats2half2_rn(tl[2 * tx][n], tl[2 * tx + 1][n]);
        *(__half2*)&out[(size_t)(n0 + n) * K + k0 + 2 * tx] = h;
    }
}

// ---------------- LayerNorm (fp32 in, fp16 out) --------------------------------
__global__ void __launch_bounds__(256)
ln_h(const float* __restrict__ in, const float* __restrict__ w,
     const float* __restrict__ b, __half* __restrict__ out)
{
    int row = blockIdx.x;
    int t = threadIdx.x;
    const float4* ip = (const float4*)(in + (size_t)row * DIM);
    float4 x = ip[t];
    float s  = x.x + x.y + x.z + x.w;
    float ss = x.x*x.x + x.y*x.y + x.z*x.z + x.w*x.w;
    #pragma unroll
    for (int off = 16; off; off >>= 1) {
        s  += __shfl_xor_sync(0xFFFFFFFFu, s,  off);
        ss += __shfl_xor_sync(0xFFFFFFFFu, ss, off);
    }
    __shared__ float sh_s[8], sh_ss[8];
    int wid = t >> 5, lid = t & 31;
    if (lid == 0) { sh_s[wid] = s; sh_ss[wid] = ss; }
    __syncthreads();
    float S = 0.f, SS = 0.f;
    #pragma unroll
    for (int i = 0; i < 8; i++) { S += sh_s[i]; SS += sh_ss[i]; }
    float mean = S * (1.0f / DIM);
    float var  = SS * (1.0f / DIM) - mean * mean;
    float inv  = rsqrtf(var + 1e-6f);
    float4 wv = ((const float4*)w)[t];
    float4 bv = ((const float4*)b)[t];
    __half2* op = (__half2*)(out + (size_t)row * DIM + 4 * t);
    op[0] = __floats2half2_rn((x.x - mean) * inv * wv.x + bv.x,
                              (x.y - mean) * inv * wv.y + bv.y);
    op[1] = __floats2half2_rn((x.z - mean) * inv * wv.z + bv.z,
                              (x.w - mean) * inv * wv.w + bv.w);
}

// ---------------- FP16 GEMM with ldmatrix fragments (R10 verified) -------------
#define HSTRIDE 72
#define OPH (128 * HSTRIDE)
#define STGH (2 * OPH)
#define STB (STGH * 2)
#define NST 3
#define GEMM_SMEM (NST * STB)        // 110592 B

template<int EPI, typename OutT>
__global__ void __launch_bounds__(256, 2)
gemm_h(const __half* __restrict__ A, const __half* __restrict__ Bt,
       const float* __restrict__ bias, const float* __restrict__ res,
       OutT* __restrict__ C, int M, int N, int K)
{
    extern __shared__ __half smh[];
    const uint32_t sb = smem_u32(smh);

    const int t = threadIdx.x;
    const int lane = t & 31, w = t >> 5;
    const int wr = w >> 2, wc = w & 3;
    const int g = lane >> 2, c = lane & 3;
    const int row0 = blockIdx.y * 128, col0 = blockIdx.x * 128;
    const int nk = K / 64;

    const int a_r = (lane & 7) + ((lane >> 3) & 1) * 8;
    const int a_c = (lane >> 4) * 8;
    const int b_n = (lane & 7) + (lane >> 4) * 8;
    const int b_k = ((lane >> 3) & 1) * 8;

    const int prow = t >> 3, pch = t & 7;
    const __half* aS = A  + (size_t)(row0 + prow) * K + pch * 8;
    const __half* bS = Bt + (size_t)(col0 + prow) * K + pch * 8;
    const uint32_t aD = sb + prow * (HSTRIDE * 2) + pch * 16;
    const uint32_t bD = aD + OPH * 2;

    float acc[4][4][4];
    #pragma unroll
    for (int i = 0; i < 4; i++)
        #pragma unroll
        for (int j = 0; j < 4; j++)
            #pragma unroll
            for (int q = 0; q < 4; q++) acc[i][j][q] = 0.f;

    #pragma unroll
    for (int pt = 0; pt < 2; pt++) {
        #pragma unroll
        for (int j = 0; j < 4; j++)
            cpa16(aD + pt * STB + j * 32 * (HSTRIDE * 2), aS + pt * 64 + (size_t)j * 32 * K);
        #pragma unroll
        for (int j = 0; j < 4; j++)
            cpa16(bD + pt * STB + j * 32 * (HSTRIDE * 2), bS + pt * 64 + (size_t)j * 32 * K);
        asm volatile("cp.async.commit_group;");
    }

    int s = 0;
    #pragma unroll 1
    for (int kt = 0; kt < nk; kt++) {
        asm volatile("cp.async.wait_group 1;");
        __syncthreads();

        const uint32_t AbU = sb + s * STB;
        const uint32_t BbU = AbU + OPH * 2;
        const uint32_t aBase = AbU + ((wr * 64 + a_r) * HSTRIDE + a_c) * 2;
        const uint32_t bBase = BbU + ((wc * 32 + b_n) * HSTRIDE + b_k) * 2;

        #pragma unroll
        for (int kk = 0; kk < 4; kk++) {
            uint32_t af[4][4], bf[2][4];
            #pragma unroll
            for (int mt = 0; mt < 4; mt++)
                ldsm4(af[mt], aBase + mt * 16 * (HSTRIDE * 2) + kk * 32);
            #pragma unroll
            for (int nt2 = 0; nt2 < 2; nt2++)
                ldsm4(bf[nt2], bBase + nt2 * 16 * (HSTRIDE * 2) + kk * 32);
            #pragma unroll
            for (int mt = 0; mt < 4; mt++)
                #pragma unroll
                for (int nt = 0; nt < 4; nt++)
                    mma16(acc[mt][nt], af[mt],
                          bf[nt >> 1][(nt & 1) * 2], bf[nt >> 1][(nt & 1) * 2 + 1]);
        }

        if (kt + 2 < nk) {
            const int sp = (s + 2) % NST;
            const int kg = (kt + 2) * 64;
            #pragma unroll
            for (int j = 0; j < 4; j++)
                cpa16(aD + sp * STB + j * 32 * (HSTRIDE * 2), aS + kg + (size_t)j * 32 * K);
            #pragma unroll
            for (int j = 0; j < 4; j++)
                cpa16(bD + sp * STB + j * 32 * (HSTRIDE * 2), bS + kg + (size_t)j * 32 * K);
        }
        asm volatile("cp.async.commit_group;");

        if (++s == NST) s = 0;
    }

    #pragma unroll
    for (int mt = 0; mt < 4; mt++) {
        int r1 = row0 + wr * 64 + mt * 16 + g;
        int r2 = r1 + 8;
        #pragma unroll
        for (int nt = 0; nt < 4; nt++) {
            int col = col0 + wc * 32 + nt * 8 + 2 * c;
            float2 bv = *(const float2*)&bias[col];
            float v0 = acc[mt][nt][0] + bv.x;
            float v1 = acc[mt][nt][1] + bv.y;
            float v2 = acc[mt][nt][2] + bv.x;
            float v3 = acc[mt][nt][3] + bv.y;
            if (EPI == 1) {
                v0 = gelu_f(v0); v1 = gelu_f(v1); v2 = gelu_f(v2); v3 = gelu_f(v3);
            } else if (EPI == 2) {
                float2 ra = *(const float2*)&res[(size_t)r1 * N + col];
                float2 rb = *(const float2*)&res[(size_t)r2 * N + col];
                v0 += ra.x; v1 += ra.y; v2 += rb.x; v3 += rb.y;
            }
            storeC(C, (size_t)r1 * N + col, v0, v1);
            storeC(C, (size_t)r2 * N + col, v2, v3);
        }
    }
}

// ---------------- Flash attention: ldmatrix K, double-buffered K/V (R10) -------
#define KVB (64 * HSTRIDE * 2)

__global__ void __launch_bounds__(256)
attn_h(const __half* __restrict__ qkv, __half* __restrict__ out)
{
    __shared__ __half ks[2][64][HSTRIDE];
    __shared__ __half vs[2][64][HSTRIDE];

    const int t = threadIdx.x, lane = t & 31, w = t >> 5;
    const int g = lane >> 2, c = lane & 3;
    const int bq = blockIdx.x * 128;
    const int b = blockIdx.y >> 4, h = blockIdx.y & 15;
    const int qg0 = bq + w * 16 + g;

    const uint32_t ksb = smem_u32(&ks[0][0][0]);
    const uint32_t vsb = smem_u32(&vs[0][0][0]);

    const int b_n = (lane & 7) + (lane >> 4) * 8;
    const int b_k = ((lane >> 3) & 1) * 8;
    const int lm_r = ((lane >> 3) & 1) * 8 + (lane & 7);
    const int lm_jofs = (lane >> 4);

    uint32_t aq[4][4];
    {
        const __half* q0p = qkv + ((size_t)(b * SEQ + qg0)) * (3 * DIM) + h * 64;
        const __half* q1p = q0p + (size_t)8 * (3 * DIM);
        const __half2 sc = __half2half2(__float2half(0.125f));
        #pragma unroll
        for (int kk = 0; kk < 4; kk++) {
            __half2 v0 = __hmul2(*(const __half2*)(q0p + kk * 16 + 2 * c), sc);
            __half2 v1 = __hmul2(*(const __half2*)(q1p + kk * 16 + 2 * c), sc);
            __half2 v2 = __hmul2(*(const __half2*)(q0p + kk * 16 + 2 * c + 8), sc);
            __half2 v3 = __hmul2(*(const __half2*)(q1p + kk * 16 + 2 * c + 8), sc);
            aq[kk][0] = *(uint32_t*)&v0; aq[kk][1] = *(uint32_t*)&v1;
            aq[kk][2] = *(uint32_t*)&v2; aq[kk][3] = *(uint32_t*)&v3;
        }
    }

    float o[8][4];
    #pragma unroll
    for (int i = 0; i < 8; i++) { o[i][0] = o[i][1] = o[i][2] = o[i][3] = 0.f; }
    float m0 = -1e30f, m1 = -1e30f, l0 = 0.f, l1 = 0.f;

    const int lrow0 = t >> 3, lch = t & 7;
    const int kend = blockIdx.x * 2 + 1;

    {
        #pragma unroll
        for (int j = 0; j < 2; j++) {
            int row = lrow0 + 32 * j;
            const __half* kp = qkv + ((size_t)(b * SEQ + row)) * (3 * DIM)
                               + DIM + h * 64 + lch * 8;
            cpa16(ksb + row * (HSTRIDE * 2) + lch * 16, kp);
            cpa16(vsb + row * (HSTRIDE * 2) + lch * 16, kp + DIM);
        }
        asm volatile("cp.async.commit_group;");
    }

    #pragma unroll 1
    for (int kt = 0; kt <= kend; kt++) {
        const int bi = kt & 1;
        if (kt < kend) {
            const int ni = (kt + 1) & 1;
            #pragma unroll
            for (int j = 0; j < 2; j++) {
                int row = lrow0 + 32 * j;
                const __half* kp = qkv + ((size_t)(b * SEQ + (kt + 1) * 64 + row)) * (3 * DIM)
                                   + DIM + h * 64 + lch * 8;
                cpa16(ksb + ni * KVB + row * (HSTRIDE * 2) + lch * 16, kp);
                cpa16(vsb + ni * KVB + row * (HSTRIDE * 2) + lch * 16, kp + DIM);
            }
        }
        asm volatile("cp.async.commit_group; cp.async.wait_group 1;");
        __syncthreads();

        float sacc[8][4];
        #pragma unroll
        for (int i = 0; i < 8; i++) { sacc[i][0] = sacc[i][1] = sacc[i][2] = sacc[i][3] = 0.f; }
        const uint32_t kBase = ksb + bi * KVB + (b_n * HSTRIDE + b_k) * 2;
        #pragma unroll
        for (int kk = 0; kk < 4; kk++) {
            uint32_t kf[4][4];
            #pragma unroll
            for (int nt2 = 0; nt2 < 4; nt2++)
                ldsm4(kf[nt2], kBase + nt2 * 16 * (HSTRIDE * 2) + kk * 32);
            #pragma unroll
            for (int nt = 0; nt < 8; nt++)
                mma16(sacc[nt], aq[kk],
                      kf[nt >> 1][(nt & 1) * 2], kf[nt >> 1][(nt & 1) * 2 + 1]);
        }

        if (kt * 64 + 63 > bq + w * 16) {
            #pragma unroll
            for (int nt = 0; nt < 8; nt++) {
                int colb = kt * 64 + nt * 8 + 2 * c;
                if (colb     > qg0)     sacc[nt][0] = -1e30f;
                if (colb + 1 > qg0)     sacc[nt][1] = -1e30f;
                if (colb     > qg0 + 8) sacc[nt][2] = -1e30f;
                if (colb + 1 > qg0 + 8) sacc[nt][3] = -1e30f;
            }
        }

        float mx0 = -1e30f, mx1 = -1e30f;
        #pragma unroll
        for (int nt = 0; nt < 8; nt++) {
            mx0 = fmaxf(mx0, fmaxf(sacc[nt][0], sacc[nt][1]));
            mx1 = fmaxf(mx1, fmaxf(sacc[nt][2], sacc[nt][3]));
        }
        mx0 = fmaxf(mx0, __shfl_xor_sync(0xFFFFFFFFu, mx0, 1));
        mx0 = fmaxf(mx0, __shfl_xor_sync(0xFFFFFFFFu, mx0, 2));
        mx1 = fmaxf(mx1, __shfl_xor_sync(0xFFFFFFFFu, mx1, 1));
        mx1 = fmaxf(mx1, __shfl_xor_sync(0xFFFFFFFFu, mx1, 2));
        float nm0 = fmaxf(m0, mx0), nm1 = fmaxf(m1, mx1);
        float al0 = __expf(m0 - nm0), al1 = __expf(m1 - nm1);
        m0 = nm0; m1 = nm1;

        float ls0 = 0.f, ls1 = 0.f;
        uint32_t pa[4][4];
        #pragma unroll
        for (int nt = 0; nt < 8; nt++) {
            float p0 = __expf(sacc[nt][0] - nm0);
            float p1 = __expf(sacc[nt][1] - nm0);
            float p2 = __expf(sacc[nt][2] - nm1);
            float p3 = __expf(sacc[nt][3] - nm1);
            ls0 += p0 + p1; ls1 += p2 + p3;
            const int kk = nt >> 1;
            if ((nt & 1) == 0) {
                pa[kk][0] = packh2(p0, p1);
                pa[kk][1] = packh2(p2, p3);
            } else {
                pa[kk][2] = packh2(p0, p1);
                pa[kk][3] = packh2(p2, p3);
            }
            o[nt][0] *= al0; o[nt][1] *= al0;
            o[nt][2] *= al1; o[nt][3] *= al1;
        }
        ls0 += __shfl_xor_sync(0xFFFFFFFFu, ls0, 1);
        ls0 += __shfl_xor_sync(0xFFFFFFFFu, ls0, 2);
        ls1 += __shfl_xor_sync(0xFFFFFFFFu, ls1, 1);
        ls1 += __shfl_xor_sync(0xFFFFFFFFu, ls1, 2);
        l0 = l0 * al0 + ls0;
        l1 = l1 * al1 + ls1;

        const uint32_t vBase = vsb + bi * KVB;
        #pragma unroll
        for (int kk = 0; kk < 4; kk++) {
            #pragma unroll
            for (int j = 0; j < 8; j += 2) {
                uint32_t r0, r1, r2, r3;
                uint32_t addr = vBase + (kk * 16 + lm_r) * (HSTRIDE * 2)
                              + (j + lm_jofs) * 8 * 2;
                asm volatile(
                    "ldmatrix.sync.aligned.m8n8.x4.trans.shared.b16 {%0,%1,%2,%3}, [%4];"
                    : "=r"(r0), "=r"(r1), "=r"(r2), "=r"(r3) : "r"(addr));
                mma16(o[j],     pa[kk], r0, r1);
                mma16(o[j + 1], pa[kk], r2, r3);
            }
        }
        __syncthreads();
    }

    float il0 = 1.0f / l0, il1 = 1.0f / l1;
    size_t o0 = ((size_t)(b * SEQ + qg0)) * DIM + h * 64;
    size_t o1 = o0 + (size_t)8 * DIM;
    #pragma unroll
    for (int nt = 0; nt < 8; nt++) {
        int cl = nt * 8 + 2 * c;
        *(__half2*)&out[o0 + cl] = __floats2half2_rn(o[nt][0] * il0, o[nt][1] * il0);
        *(__half2*)&out[o1 + cl] = __floats2half2_rn(o[nt][2] * il1, o[nt][3] * il1);
    }
}

// ---------------- Launch -------------------------------------------------------
extern "C" void kernel_launch(void* const* d_in, const int* in_sizes, int n_in,
                              void* d_out, int out_size)
{
    const float* hidden    = (const float*)d_in[0];
    const float* w_attn    = (const float*)d_in[1];
    const float* b_attn    = (const float*)d_in[2];
    const float* w_proj    = (const float*)d_in[3];
    const float* b_proj    = (const float*)d_in[4];
    const float* w_fc      = (const float*)d_in[5];
    const float* b_fc      = (const float*)d_in[6];
    const float* w_fc_proj = (const float*)d_in[7];
    const float* b_fc_proj = (const float*)d_in[8];
    const float* ln1_w     = (const float*)d_in[9];
    const float* ln1_b     = (const float*)d_in[10];
    const float* ln2_w     = (const float*)d_in[11];
    const float* ln2_b     = (const float*)d_in[12];
    float* outp            = (float*)d_out;

    __half *px, *pqkv, *patt, *py, *pfc, *pwa, *pwp, *pwf, *pwfp;
    float *ph;
    cudaGetSymbolAddress((void**)&px,   g_x);
    cudaGetSymbolAddress((void**)&pqkv, g_qkv);
    cudaGetSymbolAddress((void**)&patt, g_att);
    cudaGetSymbolAddress((void**)&ph,   g_h);
    cudaGetSymbolAddress((void**)&py,   g_y);
    cudaGetSymbolAddress((void**)&pfc,  g_fc);
    cudaGetSymbolAddress((void**)&pwa,  g_waT);
    cudaGetSymbolAddress((void**)&pwp,  g_wpT);
    cudaGetSymbolAddress((void**)&pwf,  g_wfT);
    cudaGetSymbolAddress((void**)&pwfp, g_wfpT);

    cudaFuncSetAttribute(gemm_h<0, __half>, cudaFuncAttributeMaxDynamicSharedMemorySize, GEMM_SMEM);
    cudaFuncSetAttribute(gemm_h<1, __half>, cudaFuncAttributeMaxDynamicSharedMemorySize, GEMM_SMEM);
    cudaFuncSetAttribute(gemm_h<2, float>,  cudaFuncAttributeMaxDynamicSharedMemorySize, GEMM_SMEM);

    // weight convert+transpose (half2 stores): in [K,N] -> out [N,K]
    wconv_t<<<dim3(3 * DIM / 32, DIM / 64), dim3(32, 8)>>>(w_attn,    pwa,  DIM, 3 * DIM);
    wconv_t<<<dim3(DIM / 32,     DIM / 64), dim3(32, 8)>>>(w_proj,    pwp,  DIM, DIM);
    wconv_t<<<dim3(DFF / 32,     DIM / 64), dim3(32, 8)>>>(w_fc,      pwf,  DIM, DFF);
    wconv_t<<<dim3(DIM / 32,     DFF / 64), dim3(32, 8)>>>(w_fc_proj, pwfp, DFF, DIM);

    ln_h<<<MROWS, 256>>>(hidden, ln1_w, ln1_b, px);

    gemm_h<0, __half><<<dim3(3 * DIM / 128, MROWS / 128), 256, GEMM_SMEM>>>(
        px, pwa, b_attn, nullptr, pqkv, MROWS, 3 * DIM, DIM);

    attn_h<<<dim3(SEQ / 128, BS_ * NH), 256>>>(pqkv, patt);

    gemm_h<2, float><<<dim3(DIM / 128, MROWS / 128), 256, GEMM_SMEM>>>(
        patt, pwp, b_proj, hidden, ph, MROWS, DIM, DIM);

    ln_h<<<MROWS, 256>>>(ph, ln2_w, ln2_b, py);

    gemm_h<1, __half><<<dim3(DFF / 128, MROWS / 128), 256, GEMM_SMEM>>>(
        py, pwf, b_fc, nullptr, pfc, MROWS, DFF, DIM);

    gemm_h<2, float><<<dim3(DIM / 128, MROWS / 128), 256, GEMM_SMEM>>>(
        pfc, pwfp, b_fc_proj, ph, outp, MROWS, DIM, DFF);
}

// round 16
// speedup vs baseline: 1.1241x; 1.0537x over previous
#include <cuda_runtime.h>
#include <cuda_fp16.h>
#include <math.h>
#include <stdint.h>

#define BS_  2
#define SEQ  2048
#define DIM  1024
#define NH   16
#define DFF  4096
#define MROWS (BS_*SEQ)   // 4096

// ---------------- Scratch ------------------------------------------------------
__device__ __half g_x  [MROWS * DIM];
__device__ __half g_qkv[MROWS * 3 * DIM];
__device__ __half g_att[MROWS * DIM];
__device__ float  g_h  [MROWS * DIM];
__device__ __half g_y  [MROWS * DIM];
__device__ __half g_fc [MROWS * DFF];
__device__ __half g_waT [3 * DIM * DIM];   // [N,K] fp16
__device__ __half g_wpT [DIM * DIM];
__device__ __half g_wfT [DFF * DIM];
__device__ __half g_wfpT[DIM * DFF];

// ---------------- helpers ------------------------------------------------------
__device__ __forceinline__ void mma16(float d[4], const uint32_t a[4],
                                      uint32_t b0, uint32_t b1) {
    asm volatile("mma.sync.aligned.m16n8k16.row.col.f32.f16.f16.f32 "
        "{%0,%1,%2,%3}, {%4,%5,%6,%7}, {%8,%9}, {%0,%1,%2,%3};\n"
        : "+f"(d[0]), "+f"(d[1]), "+f"(d[2]), "+f"(d[3])
        : "r"(a[0]), "r"(a[1]), "r"(a[2]), "r"(a[3]), "r"(b0), "r"(b1));
}
__device__ __forceinline__ void ldsm4(uint32_t r[4], uint32_t addr) {
    asm volatile("ldmatrix.sync.aligned.m8n8.x4.shared.b16 {%0,%1,%2,%3}, [%4];"
        : "=r"(r[0]), "=r"(r[1]), "=r"(r[2]), "=r"(r[3]) : "r"(addr));
}
__device__ __forceinline__ float gelu_f(float x) {
    float x3 = x * x * x;
    return 0.5f * x * (1.0f + tanhf(0.7978845608028654f * (x + 0.044715f * x3)));
}
__device__ __forceinline__ uint32_t smem_u32(const void* p) {
    uint32_t a;
    asm("{ .reg .u64 t; cvta.to.shared.u64 t, %1; cvt.u32.u64 %0, t; }" : "=r"(a) : "l"(p));
    return a;
}
__device__ __forceinline__ void cpa16(uint32_t dst, const void* src) {
    asm volatile("cp.async.cg.shared.global [%0], [%1], 16;" :: "r"(dst), "l"(src));
}
__device__ __forceinline__ uint32_t packh2(float a, float b) {
    __half2 h = __floats2half2_rn(a, b);
    return *(uint32_t*)&h;
}
__device__ __forceinline__ void storeC(float* C, size_t idx, float v0, float v1) {
    *(float2*)&C[idx] = make_float2(v0, v1);
}
__device__ __forceinline__ void storeC(__half* C, size_t idx, float v0, float v1) {
    *(__half2*)&C[idx] = __floats2half2_rn(v0, v1);
}

// ---------------- weight convert + transpose (half2 stores) --------------------
__global__ void __launch_bounds__(256)
wconv_t(const float* __restrict__ in, __half* __restrict__ out, int K, int N)
{
    __shared__ float tl[64][33];
    const int tx = threadIdx.x, ty = threadIdx.y;
    const int n0 = blockIdx.x * 32, k0 = blockIdx.y * 64;
    #pragma unroll
    for (int j = 0; j < 8; j++) {
        int kr = ty + 8 * j;
        tl[kr][tx] = in[(size_t)(k0 + kr) * N + n0 + tx];
    }
    __syncthreads();
    #pragma unroll
    for (int j = 0; j < 4; j++) {
        int n = ty + 8 * j;
        __half2 h = __floats2half2_rn(tl[2 * tx][n], tl[2 * tx + 1][n]);
        *(__half2*)&out[(size_t)(n0 + n) * K + k0 + 2 * tx] = h;
    }
}

// ---------------- LayerNorm (fp32 in, fp16 out) --------------------------------
__global__ void __launch_bounds__(256)
ln_h(const float* __restrict__ in, const float* __restrict__ w,
     const float* __restrict__ b, __half* __restrict__ out)
{
    int row = blockIdx.x;
    int t = threadIdx.x;
    const float4* ip = (const float4*)(in + (size_t)row * DIM);
    float4 x = ip[t];
    float s  = x.x + x.y + x.z + x.w;
    float ss = x.x*x.x + x.y*x.y + x.z*x.z + x.w*x.w;
    #pragma unroll
    for (int off = 16; off; off >>= 1) {
        s  += __shfl_xor_sync(0xFFFFFFFFu, s,  off);
        ss += __shfl_xor_sync(0xFFFFFFFFu, ss, off);
    }
    __shared__ float sh_s[8], sh_ss[8];
    int wid = t >> 5, lid = t & 31;
    if (lid == 0) { sh_s[wid] = s; sh_ss[wid] = ss; }
    __syncthreads();
    float S = 0.f, SS = 0.f;
    #pragma unroll
    for (int i = 0; i < 8; i++) { S += sh_s[i]; SS += sh_ss[i]; }
    float mean = S * (1.0f / DIM);
    float var  = SS * (1.0f / DIM) - mean * mean;
    float inv  = rsqrtf(var + 1e-6f);
    float4 wv = ((const float4*)w)[t];
    float4 bv = ((const float4*)b)[t];
    __half2* op = (__half2*)(out + (size_t)row * DIM + 4 * t);
    op[0] = __floats2half2_rn((x.x - mean) * inv * wv.x + bv.x,
                              (x.y - mean) * inv * wv.y + bv.y);
    op[1] = __floats2half2_rn((x.z - mean) * inv * wv.z + bv.z,
                              (x.w - mean) * inv * wv.w + bv.w);
}

// ---------------- FP16 GEMM with ldmatrix fragments (R10 verified) -------------
#define HSTRIDE 72
#define OPH (128 * HSTRIDE)
#define STGH (2 * OPH)
#define STB (STGH * 2)
#define NST 3
#define GEMM_SMEM (NST * STB)        // 110592 B

template<int EPI, typename OutT>
__global__ void __launch_bounds__(256, 2)
gemm_h(const __half* __restrict__ A, const __half* __restrict__ Bt,
       const float* __restrict__ bias, const float* __restrict__ res,
       OutT* __restrict__ C, int M, int N, int K)
{
    extern __shared__ __half smh[];
    const uint32_t sb = smem_u32(smh);

    const int t = threadIdx.x;
    const int lane = t & 31, w = t >> 5;
    const int wr = w >> 2, wc = w & 3;
    const int g = lane >> 2, c = lane & 3;
    const int row0 = blockIdx.y * 128, col0 = blockIdx.x * 128;
    const int nk = K / 64;

    const int a_r = (lane & 7) + ((lane >> 3) & 1) * 8;
    const int a_c = (lane >> 4) * 8;
    const int b_n = (lane & 7) + (lane >> 4) * 8;
    const int b_k = ((lane >> 3) & 1) * 8;

    const int prow = t >> 3, pch = t & 7;
    const __half* aS = A  + (size_t)(row0 + prow) * K + pch * 8;
    const __half* bS = Bt + (size_t)(col0 + prow) * K + pch * 8;
    const uint32_t aD = sb + prow * (HSTRIDE * 2) + pch * 16;
    const uint32_t bD = aD + OPH * 2;

    float acc[4][4][4];
    #pragma unroll
    for (int i = 0; i < 4; i++)
        #pragma unroll
        for (int j = 0; j < 4; j++)
            #pragma unroll
            for (int q = 0; q < 4; q++) acc[i][j][q] = 0.f;

    #pragma unroll
    for (int pt = 0; pt < 2; pt++) {
        #pragma unroll
        for (int j = 0; j < 4; j++)
            cpa16(aD + pt * STB + j * 32 * (HSTRIDE * 2), aS + pt * 64 + (size_t)j * 32 * K);
        #pragma unroll
        for (int j = 0; j < 4; j++)
            cpa16(bD + pt * STB + j * 32 * (HSTRIDE * 2), bS + pt * 64 + (size_t)j * 32 * K);
        asm volatile("cp.async.commit_group;");
    }

    int s = 0;
    #pragma unroll 1
    for (int kt = 0; kt < nk; kt++) {
        asm volatile("cp.async.wait_group 1;");
        __syncthreads();

        const uint32_t AbU = sb + s * STB;
        const uint32_t BbU = AbU + OPH * 2;
        const uint32_t aBase = AbU + ((wr * 64 + a_r) * HSTRIDE + a_c) * 2;
        const uint32_t bBase = BbU + ((wc * 32 + b_n) * HSTRIDE + b_k) * 2;

        #pragma unroll
        for (int kk = 0; kk < 4; kk++) {
            uint32_t af[4][4], bf[2][4];
            #pragma unroll
            for (int mt = 0; mt < 4; mt++)
                ldsm4(af[mt], aBase + mt * 16 * (HSTRIDE * 2) + kk * 32);
            #pragma unroll
            for (int nt2 = 0; nt2 < 2; nt2++)
                ldsm4(bf[nt2], bBase + nt2 * 16 * (HSTRIDE * 2) + kk * 32);
            #pragma unroll
            for (int mt = 0; mt < 4; mt++)
                #pragma unroll
                for (int nt = 0; nt < 4; nt++)
                    mma16(acc[mt][nt], af[mt],
                          bf[nt >> 1][(nt & 1) * 2], bf[nt >> 1][(nt & 1) * 2 + 1]);
        }

        if (kt + 2 < nk) {
            const int sp = (s + 2) % NST;
            const int kg = (kt + 2) * 64;
            #pragma unroll
            for (int j = 0; j < 4; j++)
                cpa16(aD + sp * STB + j * 32 * (HSTRIDE * 2), aS + kg + (size_t)j * 32 * K);
            #pragma unroll
            for (int j = 0; j < 4; j++)
                cpa16(bD + sp * STB + j * 32 * (HSTRIDE * 2), bS + kg + (size_t)j * 32 * K);
        }
        asm volatile("cp.async.commit_group;");

        if (++s == NST) s = 0;
    }

    #pragma unroll
    for (int mt = 0; mt < 4; mt++) {
        int r1 = row0 + wr * 64 + mt * 16 + g;
        int r2 = r1 + 8;
        #pragma unroll
        for (int nt = 0; nt < 4; nt++) {
            int col = col0 + wc * 32 + nt * 8 + 2 * c;
            float2 bv = *(const float2*)&bias[col];
            float v0 = acc[mt][nt][0] + bv.x;
            float v1 = acc[mt][nt][1] + bv.y;
            float v2 = acc[mt][nt][2] + bv.x;
            float v3 = acc[mt][nt][3] + bv.y;
            if (EPI == 1) {
                v0 = gelu_f(v0); v1 = gelu_f(v1); v2 = gelu_f(v2); v3 = gelu_f(v3);
            } else if (EPI == 2) {
                float2 ra = *(const float2*)&res[(size_t)r1 * N + col];
                float2 rb = *(const float2*)&res[(size_t)r2 * N + col];
                v0 += ra.x; v1 += ra.y; v2 += rb.x; v3 += rb.y;
            }
            storeC(C, (size_t)r1 * N + col, v0, v1);
            storeC(C, (size_t)r2 * N + col, v2, v3);
        }
    }
}

// ---------------- Flash attention: work-balanced (paired q-tiles) --------------
// grid (SEQ/256, B*NH): CTA bx processes q-tiles {bx, 15-bx} -> uniform 34 K-tiles.
#define KVB (64 * HSTRIDE * 2)
#define NQT (SEQ / 128)              // 16 q-tiles

__global__ void __launch_bounds__(256)
attn_h(const __half* __restrict__ qkv, __half* __restrict__ out)
{
    __shared__ __half ks[2][64][HSTRIDE];
    __shared__ __half vs[2][64][HSTRIDE];

    const int t = threadIdx.x, lane = t & 31, w = t >> 5;
    const int g = lane >> 2, c = lane & 3;
    const int b = blockIdx.y >> 4, h = blockIdx.y & 15;

    const uint32_t ksb = smem_u32(&ks[0][0][0]);
    const uint32_t vsb = smem_u32(&vs[0][0][0]);

    const int b_n = (lane & 7) + (lane >> 4) * 8;
    const int b_k = ((lane >> 3) & 1) * 8;
    const int lm_r = ((lane >> 3) & 1) * 8 + (lane & 7);
    const int lm_jofs = (lane >> 4);
    const int lrow0 = t >> 3, lch = t & 7;

    #pragma unroll 1
    for (int pass = 0; pass < 2; pass++) {
        const int qtile = pass == 0 ? (int)blockIdx.x : (NQT - 1 - (int)blockIdx.x);
        const int bq = qtile * 128;
        const int qg0 = bq + w * 16 + g;
        const int kend = qtile * 2 + 1;

        // Q fragments, pre-scaled by 1/8
        uint32_t aq[4][4];
        {
            const __half* q0p = qkv + ((size_t)(b * SEQ + qg0)) * (3 * DIM) + h * 64;
            const __half* q1p = q0p + (size_t)8 * (3 * DIM);
            const __half2 sc = __half2half2(__float2half(0.125f));
            #pragma unroll
            for (int kk = 0; kk < 4; kk++) {
                __half2 v0 = __hmul2(*(const __half2*)(q0p + kk * 16 + 2 * c), sc);
                __half2 v1 = __hmul2(*(const __half2*)(q1p + kk * 16 + 2 * c), sc);
                __half2 v2 = __hmul2(*(const __half2*)(q0p + kk * 16 + 2 * c + 8), sc);
                __half2 v3 = __hmul2(*(const __half2*)(q1p + kk * 16 + 2 * c + 8), sc);
                aq[kk][0] = *(uint32_t*)&v0; aq[kk][1] = *(uint32_t*)&v1;
                aq[kk][2] = *(uint32_t*)&v2; aq[kk][3] = *(uint32_t*)&v3;
            }
        }

        float o[8][4];
        #pragma unroll
        for (int i = 0; i < 8; i++) { o[i][0] = o[i][1] = o[i][2] = o[i][3] = 0.f; }
        float m0 = -1e30f, m1 = -1e30f, l0 = 0.f, l1 = 0.f;

        // prologue: K/V tile 0 -> buffer 0
        {
            #pragma unroll
            for (int j = 0; j < 2; j++) {
                int row = lrow0 + 32 * j;
                const __half* kp = qkv + ((size_t)(b * SEQ + row)) * (3 * DIM)
                                   + DIM + h * 64 + lch * 8;
                cpa16(ksb + row * (HSTRIDE * 2) + lch * 16, kp);
                cpa16(vsb + row * (HSTRIDE * 2) + lch * 16, kp + DIM);
            }
            asm volatile("cp.async.commit_group;");
        }

        #pragma unroll 1
        for (int kt = 0; kt <= kend; kt++) {
            const int bi = kt & 1;
            if (kt < kend) {
                const int ni = (kt + 1) & 1;
                #pragma unroll
                for (int j = 0; j < 2; j++) {
                    int row = lrow0 + 32 * j;
                    const __half* kp = qkv + ((size_t)(b * SEQ + (kt + 1) * 64 + row)) * (3 * DIM)
                                       + DIM + h * 64 + lch * 8;
                    cpa16(ksb + ni * KVB + row * (HSTRIDE * 2) + lch * 16, kp);
                    cpa16(vsb + ni * KVB + row * (HSTRIDE * 2) + lch * 16, kp + DIM);
                }
            }
            asm volatile("cp.async.commit_group; cp.async.wait_group 1;");
            __syncthreads();

            float sacc[8][4];
            #pragma unroll
            for (int i = 0; i < 8; i++) { sacc[i][0] = sacc[i][1] = sacc[i][2] = sacc[i][3] = 0.f; }
            const uint32_t kBase = ksb + bi * KVB + (b_n * HSTRIDE + b_k) * 2;
            #pragma unroll
            for (int kk = 0; kk < 4; kk++) {
                uint32_t kf[4][4];
                #pragma unroll
                for (int nt2 = 0; nt2 < 4; nt2++)
                    ldsm4(kf[nt2], kBase + nt2 * 16 * (HSTRIDE * 2) + kk * 32);
                #pragma unroll
                for (int nt = 0; nt < 8; nt++)
                    mma16(sacc[nt], aq[kk],
                          kf[nt >> 1][(nt & 1) * 2], kf[nt >> 1][(nt & 1) * 2 + 1]);
            }

            if (kt * 64 + 63 > bq + w * 16) {
                #pragma unroll
                for (int nt = 0; nt < 8; nt++) {
                    int colb = kt * 64 + nt * 8 + 2 * c;
                    if (colb     > qg0)     sacc[nt][0] = -1e30f;
                    if (colb + 1 > qg0)     sacc[nt][1] = -1e30f;
                    if (colb     > qg0 + 8) sacc[nt][2] = -1e30f;
                    if (colb + 1 > qg0 + 8) sacc[nt][3] = -1e30f;
                }
            }

            float mx0 = -1e30f, mx1 = -1e30f;
            #pragma unroll
            for (int nt = 0; nt < 8; nt++) {
                mx0 = fmaxf(mx0, fmaxf(sacc[nt][0], sacc[nt][1]));
                mx1 = fmaxf(mx1, fmaxf(sacc[nt][2], sacc[nt][3]));
            }
            mx0 = fmaxf(mx0, __shfl_xor_sync(0xFFFFFFFFu, mx0, 1));
            mx0 = fmaxf(mx0, __shfl_xor_sync(0xFFFFFFFFu, mx0, 2));
            mx1 = fmaxf(mx1, __shfl_xor_sync(0xFFFFFFFFu, mx1, 1));
            mx1 = fmaxf(mx1, __shfl_xor_sync(0xFFFFFFFFu, mx1, 2));
            float nm0 = fmaxf(m0, mx0), nm1 = fmaxf(m1, mx1);
            float al0 = __expf(m0 - nm0), al1 = __expf(m1 - nm1);
            m0 = nm0; m1 = nm1;

            float ls0 = 0.f, ls1 = 0.f;
            uint32_t pa[4][4];
            #pragma unroll
            for (int nt = 0; nt < 8; nt++) {
                float p0 = __expf(sacc[nt][0] - nm0);
                float p1 = __expf(sacc[nt][1] - nm0);
                float p2 = __expf(sacc[nt][2] - nm1);
                float p3 = __expf(sacc[nt][3] - nm1);
                ls0 += p0 + p1; ls1 += p2 + p3;
                const int kk = nt >> 1;
                if ((nt & 1) == 0) {
                    pa[kk][0] = packh2(p0, p1);
                    pa[kk][1] = packh2(p2, p3);
                } else {
                    pa[kk][2] = packh2(p0, p1);
                    pa[kk][3] = packh2(p2, p3);
                }
                o[nt][0] *= al0; o[nt][1] *= al0;
                o[nt][2] *= al1; o[nt][3] *= al1;
            }
            ls0 += __shfl_xor_sync(0xFFFFFFFFu, ls0, 1);
            ls0 += __shfl_xor_sync(0xFFFFFFFFu, ls0, 2);
            ls1 += __shfl_xor_sync(0xFFFFFFFFu, ls1, 1);
            ls1 += __shfl_xor_sync(0xFFFFFFFFu, ls1, 2);
            l0 = l0 * al0 + ls0;
            l1 = l1 * al1 + ls1;

            const uint32_t vBase = vsb + bi * KVB;
            #pragma unroll
            for (int kk = 0; kk < 4; kk++) {
                #pragma unroll
                for (int j = 0; j < 8; j += 2) {
                    uint32_t r0, r1, r2, r3;
                    uint32_t addr = vBase + (kk * 16 + lm_r) * (HSTRIDE * 2)
                                  + (j + lm_jofs) * 8 * 2;
                    asm volatile(
                        "ldmatrix.sync.aligned.m8n8.x4.trans.shared.b16 {%0,%1,%2,%3}, [%4];"
                        : "=r"(r0), "=r"(r1), "=r"(r2), "=r"(r3) : "r"(addr));
                    mma16(o[j],     pa[kk], r0, r1);
                    mma16(o[j + 1], pa[kk], r2, r3);
                }
            }
            __syncthreads();
        }

        // normalize + store
        float il0 = 1.0f / l0, il1 = 1.0f / l1;
        size_t o0 = ((size_t)(b * SEQ + qg0)) * DIM + h * 64;
        size_t o1 = o0 + (size_t)8 * DIM;
        #pragma unroll
        for (int nt = 0; nt < 8; nt++) {
            int cl = nt * 8 + 2 * c;
            *(__half2*)&out[o0 + cl] = __floats2half2_rn(o[nt][0] * il0, o[nt][1] * il0);
            *(__half2*)&out[o1 + cl] = __floats2half2_rn(o[nt][2] * il1, o[nt][3] * il1);
        }
    }
}

// ---------------- Launch -------------------------------------------------------
extern "C" void kernel_launch(void* const* d_in, const int* in_sizes, int n_in,
                              void* d_out, int out_size)
{
    const float* hidden    = (const float*)d_in[0];
    const float* w_attn    = (const float*)d_in[1];
    const float* b_attn    = (const float*)d_in[2];
    const float* w_proj    = (const float*)d_in[3];
    const float* b_proj    = (const float*)d_in[4];
    const float* w_fc      = (const float*)d_in[5];
    const float* b_fc      = (const float*)d_in[6];
    const float* w_fc_proj = (const float*)d_in[7];
    const float* b_fc_proj = (const float*)d_in[8];
    const float* ln1_w     = (const float*)d_in[9];
    const float* ln1_b     = (const float*)d_in[10];
    const float* ln2_w     = (const float*)d_in[11];
    const float* ln2_b     = (const float*)d_in[12];
    float* outp            = (float*)d_out;

    __half *px, *pqkv, *patt, *py, *pfc, *pwa, *pwp, *pwf, *pwfp;
    float *ph;
    cudaGetSymbolAddress((void**)&px,   g_x);
    cudaGetSymbolAddress((void**)&pqkv, g_qkv);
    cudaGetSymbolAddress((void**)&patt, g_att);
    cudaGetSymbolAddress((void**)&ph,   g_h);
    cudaGetSymbolAddress((void**)&py,   g_y);
    cudaGetSymbolAddress((void**)&pfc,  g_fc);
    cudaGetSymbolAddress((void**)&pwa,  g_waT);
    cudaGetSymbolAddress((void**)&pwp,  g_wpT);
    cudaGetSymbolAddress((void**)&pwf,  g_wfT);
    cudaGetSymbolAddress((void**)&pwfp, g_wfpT);

    cudaFuncSetAttribute(gemm_h<0, __half>, cudaFuncAttributeMaxDynamicSharedMemorySize, GEMM_SMEM);
    cudaFuncSetAttribute(gemm_h<1, __half>, cudaFuncAttributeMaxDynamicSharedMemorySize, GEMM_SMEM);
    cudaFuncSetAttribute(gemm_h<2, float>,  cudaFuncAttributeMaxDynamicSharedMemorySize, GEMM_SMEM);

    wconv_t<<<dim3(3 * DIM / 32, DIM / 64), dim3(32, 8)>>>(w_attn,    pwa,  DIM, 3 * DIM);
    wconv_t<<<dim3(DIM / 32,     DIM / 64), dim3(32, 8)>>>(w_proj,    pwp,  DIM, DIM);
    wconv_t<<<dim3(DFF / 32,     DIM / 64), dim3(32, 8)>>>(w_fc,      pwf,  DIM, DFF);
    wconv_t<<<dim3(DIM / 32,     DFF / 64), dim3(32, 8)>>>(w_fc_proj, pwfp, DFF, DIM);

    ln_h<<<MROWS, 256>>>(hidden, ln1_w, ln1_b, px);

    gemm_h<0, __half><<<dim3(3 * DIM / 128, MROWS / 128), 256, GEMM_SMEM>>>(
        px, pwa, b_attn, nullptr, pqkv, MROWS, 3 * DIM, DIM);

    attn_h<<<dim3(SEQ / 256, BS_ * NH), 256>>>(pqkv, patt);

    gemm_h<2, float><<<dim3(DIM / 128, MROWS / 128), 256, GEMM_SMEM>>>(
        patt, pwp, b_proj, hidden, ph, MROWS, DIM, DIM);

    ln_h<<<MROWS, 256>>>(ph, ln2_w, ln2_b, py);

    gemm_h<1, __half><<<dim3(DFF / 128, MROWS / 128), 256, GEMM_SMEM>>>(
        py, pwf, b_fc, nullptr, pfc, MROWS, DFF, DIM);

    gemm_h<2, float><<<dim3(DIM / 128, MROWS / 128), 256, GEMM_SMEM>>>(
        pfc, pwfp, b_fc_proj, ph, outp, MROWS, DIM, DFF);
}

// round 17
// speedup vs baseline: 1.1414x; 1.0153x over previous
#include <cuda_runtime.h>
#include <cuda_fp16.h>
#include <math.h>
#include <stdint.h>

#define BS_  2
#define SEQ  2048
#define DIM  1024
#define NH   16
#define DFF  4096
#define MROWS (BS_*SEQ)   // 4096

// ---------------- Scratch ------------------------------------------------------
__device__ __half g_x  [MROWS * DIM];
__device__ __half g_qkv[MROWS * 3 * DIM];
__device__ __half g_att[MROWS * DIM];
__device__ float  g_h  [MROWS * DIM];
__device__ __half g_y  [MROWS * DIM];
__device__ __half g_fc [MROWS * DFF];
__device__ __half g_waT [3 * DIM * DIM];   // [N,K] fp16
__device__ __half g_wpT [DIM * DIM];
__device__ __half g_wfT [DFF * DIM];
__device__ __half g_wfpT[DIM * DFF];

// ---------------- helpers ------------------------------------------------------
__device__ __forceinline__ void mma16(float d[4], const uint32_t a[4],
                                      uint32_t b0, uint32_t b1) {
    asm volatile("mma.sync.aligned.m16n8k16.row.col.f32.f16.f16.f32 "
        "{%0,%1,%2,%3}, {%4,%5,%6,%7}, {%8,%9}, {%0,%1,%2,%3};\n"
        : "+f"(d[0]), "+f"(d[1]), "+f"(d[2]), "+f"(d[3])
        : "r"(a[0]), "r"(a[1]), "r"(a[2]), "r"(a[3]), "r"(b0), "r"(b1));
}
__device__ __forceinline__ void ldsm4(uint32_t r[4], uint32_t addr) {
    asm volatile("ldmatrix.sync.aligned.m8n8.x4.shared.b16 {%0,%1,%2,%3}, [%4];"
        : "=r"(r[0]), "=r"(r[1]), "=r"(r[2]), "=r"(r[3]) : "r"(addr));
}
__device__ __forceinline__ float gelu_f(float x) {
    float x3 = x * x * x;
    return 0.5f * x * (1.0f + tanhf(0.7978845608028654f * (x + 0.044715f * x3)));
}
__device__ __forceinline__ uint32_t smem_u32(const void* p) {
    uint32_t a;
    asm("{ .reg .u64 t; cvta.to.shared.u64 t, %1; cvt.u32.u64 %0, t; }" : "=r"(a) : "l"(p));
    return a;
}
__device__ __forceinline__ void cpa16(uint32_t dst, const void* src) {
    asm volatile("cp.async.cg.shared.global [%0], [%1], 16;" :: "r"(dst), "l"(src));
}
__device__ __forceinline__ uint32_t packh2(float a, float b) {
    __half2 h = __floats2half2_rn(a, b);
    return *(uint32_t*)&h;
}
__device__ __forceinline__ void storeC(float* C, size_t idx, float v0, float v1) {
    *(float2*)&C[idx] = make_float2(v0, v1);
}
__device__ __forceinline__ void storeC(__half* C, size_t idx, float v0, float v1) {
    *(__half2*)&C[idx] = __floats2half2_rn(v0, v1);
}

// ---------------- merged weight convert + transpose ----------------------------
// One launch for all 4 weights. Tile 64k x 32n. Flat block index dispatch.
// Tile counts: wa (K=1024,N=3072): 96*16=1536; wp (1024,1024): 32*16=512;
//              wf (1024,4096): 128*16=2048; wfp (4096,1024): 32*64=2048.
#define WT_A0 0
#define WT_A1 1536
#define WT_A2 2048
#define WT_A3 4096
#define WT_TOT 6144

__global__ void __launch_bounds__(256)
wconv_all(const float* __restrict__ wa,  const float* __restrict__ wp,
          const float* __restrict__ wf,  const float* __restrict__ wfp,
          __half* __restrict__ oa, __half* __restrict__ op_,
          __half* __restrict__ of, __half* __restrict__ ofp)
{
    __shared__ float tl[64][33];
    const int bid = blockIdx.x;
    const float* in; __half* out; int K, N, lb;
    if (bid < WT_A1)      { in = wa;  out = oa;  K = DIM; N = 3*DIM; lb = bid; }
    else if (bid < WT_A2) { in = wp;  out = op_; K = DIM; N = DIM;   lb = bid - WT_A1; }
    else if (bid < WT_A3) { in = wf;  out = of;  K = DIM; N = DFF;   lb = bid - WT_A2; }
    else                  { in = wfp; out = ofp; K = DFF; N = DIM;   lb = bid - WT_A3; }
    const int ntx = N / 32;
    const int bx = lb % ntx, by = lb / ntx;
    const int tx = threadIdx.x, ty = threadIdx.y;
    const int n0 = bx * 32, k0 = by * 64;
    #pragma unroll
    for (int j = 0; j < 8; j++) {
        int kr = ty + 8 * j;
        tl[kr][tx] = in[(size_t)(k0 + kr) * N + n0 + tx];
    }
    __syncthreads();
    #pragma unroll
    for (int j = 0; j < 4; j++) {
        int n = ty + 8 * j;
        __half2 h = __floats2half2_rn(tl[2 * tx][n], tl[2 * tx + 1][n]);
        *(__half2*)&out[(size_t)(n0 + n) * K + k0 + 2 * tx] = h;
    }
}

// ---------------- LayerNorm (fp32 in, fp16 out) --------------------------------
__global__ void __launch_bounds__(256)
ln_h(const float* __restrict__ in, const float* __restrict__ w,
     const float* __restrict__ b, __half* __restrict__ out)
{
    int row = blockIdx.x;
    int t = threadIdx.x;
    const float4* ip = (const float4*)(in + (size_t)row * DIM);
    float4 x = ip[t];
    float s  = x.x + x.y + x.z + x.w;
    float ss = x.x*x.x + x.y*x.y + x.z*x.z + x.w*x.w;
    #pragma unroll
    for (int off = 16; off; off >>= 1) {
        s  += __shfl_xor_sync(0xFFFFFFFFu, s,  off);
        ss += __shfl_xor_sync(0xFFFFFFFFu, ss, off);
    }
    __shared__ float sh_s[8], sh_ss[8];
    int wid = t >> 5, lid = t & 31;
    if (lid == 0) { sh_s[wid] = s; sh_ss[wid] = ss; }
    __syncthreads();
    float S = 0.f, SS = 0.f;
    #pragma unroll
    for (int i = 0; i < 8; i++) { S += sh_s[i]; SS += sh_ss[i]; }
    float mean = S * (1.0f / DIM);
    float var  = SS * (1.0f / DIM) - mean * mean;
    float inv  = rsqrtf(var + 1e-6f);
    float4 wv = ((const float4*)w)[t];
    float4 bv = ((const float4*)b)[t];
    __half2* op = (__half2*)(out + (size_t)row * DIM + 4 * t);
    op[0] = __floats2half2_rn((x.x - mean) * inv * wv.x + bv.x,
                              (x.y - mean) * inv * wv.y + bv.y);
    op[1] = __floats2half2_rn((x.z - mean) * inv * wv.z + bv.z,
                              (x.w - mean) * inv * wv.w + bv.w);
}

// ---------------- FP16 GEMM with ldmatrix fragments (R10 verified) -------------
#define HSTRIDE 72
#define OPH (128 * HSTRIDE)
#define STGH (2 * OPH)
#define STB (STGH * 2)
#define NST 3
#define GEMM_SMEM (NST * STB)        // 110592 B

template<int EPI, typename OutT>
__global__ void __launch_bounds__(256, 2)
gemm_h(const __half* __restrict__ A, const __half* __restrict__ Bt,
       const float* __restrict__ bias, const float* __restrict__ res,
       OutT* __restrict__ C, int M, int N, int K)
{
    extern __shared__ __half smh[];
    const uint32_t sb = smem_u32(smh);

    const int t = threadIdx.x;
    const int lane = t & 31, w = t >> 5;
    const int wr = w >> 2, wc = w & 3;
    const int g = lane >> 2, c = lane & 3;
    const int row0 = blockIdx.y * 128, col0 = blockIdx.x * 128;
    const int nk = K / 64;

    const int a_r = (lane & 7) + ((lane >> 3) & 1) * 8;
    const int a_c = (lane >> 4) * 8;
    const int b_n = (lane & 7) + (lane >> 4) * 8;
    const int b_k = ((lane >> 3) & 1) * 8;

    const int prow = t >> 3, pch = t & 7;
    const __half* aS = A  + (size_t)(row0 + prow) * K + pch * 8;
    const __half* bS = Bt + (size_t)(col0 + prow) * K + pch * 8;
    const uint32_t aD = sb + prow * (HSTRIDE * 2) + pch * 16;
    const uint32_t bD = aD + OPH * 2;

    float acc[4][4][4];
    #pragma unroll
    for (int i = 0; i < 4; i++)
        #pragma unroll
        for (int j = 0; j < 4; j++)
            #pragma unroll
            for (int q = 0; q < 4; q++) acc[i][j][q] = 0.f;

    #pragma unroll
    for (int pt = 0; pt < 2; pt++) {
        #pragma unroll
        for (int j = 0; j < 4; j++)
            cpa16(aD + pt * STB + j * 32 * (HSTRIDE * 2), aS + pt * 64 + (size_t)j * 32 * K);
        #pragma unroll
        for (int j = 0; j < 4; j++)
            cpa16(bD + pt * STB + j * 32 * (HSTRIDE * 2), bS + pt * 64 + (size_t)j * 32 * K);
        asm volatile("cp.async.commit_group;");
    }

    int s = 0;
    #pragma unroll 1
    for (int kt = 0; kt < nk; kt++) {
        asm volatile("cp.async.wait_group 1;");
        __syncthreads();

        const uint32_t AbU = sb + s * STB;
        const uint32_t BbU = AbU + OPH * 2;
        const uint32_t aBase = AbU + ((wr * 64 + a_r) * HSTRIDE + a_c) * 2;
        const uint32_t bBase = BbU + ((wc * 32 + b_n) * HSTRIDE + b_k) * 2;

        #pragma unroll
        for (int kk = 0; kk < 4; kk++) {
            uint32_t af[4][4], bf[2][4];
            #pragma unroll
            for (int mt = 0; mt < 4; mt++)
                ldsm4(af[mt], aBase + mt * 16 * (HSTRIDE * 2) + kk * 32);
            #pragma unroll
            for (int nt2 = 0; nt2 < 2; nt2++)
                ldsm4(bf[nt2], bBase + nt2 * 16 * (HSTRIDE * 2) + kk * 32);
            #pragma unroll
            for (int mt = 0; mt < 4; mt++)
                #pragma unroll
                for (int nt = 0; nt < 4; nt++)
                    mma16(acc[mt][nt], af[mt],
                          bf[nt >> 1][(nt & 1) * 2], bf[nt >> 1][(nt & 1) * 2 + 1]);
        }

        if (kt + 2 < nk) {
            const int sp = (s + 2) % NST;
            const int kg = (kt + 2) * 64;
            #pragma unroll
            for (int j = 0; j < 4; j++)
                cpa16(aD + sp * STB + j * 32 * (HSTRIDE * 2), aS + kg + (size_t)j * 32 * K);
            #pragma unroll
            for (int j = 0; j < 4; j++)
                cpa16(bD + sp * STB + j * 32 * (HSTRIDE * 2), bS + kg + (size_t)j * 32 * K);
        }
        asm volatile("cp.async.commit_group;");

        if (++s == NST) s = 0;
    }

    #pragma unroll
    for (int mt = 0; mt < 4; mt++) {
        int r1 = row0 + wr * 64 + mt * 16 + g;
        int r2 = r1 + 8;
        #pragma unroll
        for (int nt = 0; nt < 4; nt++) {
            int col = col0 + wc * 32 + nt * 8 + 2 * c;
            float2 bv = *(const float2*)&bias[col];
            float v0 = acc[mt][nt][0] + bv.x;
            float v1 = acc[mt][nt][1] + bv.y;
            float v2 = acc[mt][nt][2] + bv.x;
            float v3 = acc[mt][nt][3] + bv.y;
            if (EPI == 1) {
                v0 = gelu_f(v0); v1 = gelu_f(v1); v2 = gelu_f(v2); v3 = gelu_f(v3);
            } else if (EPI == 2) {
                float2 ra = *(const float2*)&res[(size_t)r1 * N + col];
                float2 rb = *(const float2*)&res[(size_t)r2 * N + col];
                v0 += ra.x; v1 += ra.y; v2 += rb.x; v3 += rb.y;
            }
            storeC(C, (size_t)r1 * N + col, v0, v1);
            storeC(C, (size_t)r2 * N + col, v2, v3);
        }
    }
}

// ---------------- Flash attention: work-balanced (paired q-tiles, R16) ---------
#define KVB (64 * HSTRIDE * 2)
#define NQT (SEQ / 128)              // 16 q-tiles

__global__ void __launch_bounds__(256)
attn_h(const __half* __restrict__ qkv, __half* __restrict__ out)
{
    __shared__ __half ks[2][64][HSTRIDE];
    __shared__ __half vs[2][64][HSTRIDE];

    const int t = threadIdx.x, lane = t & 31, w = t >> 5;
    const int g = lane >> 2, c = lane & 3;
    const int b = blockIdx.y >> 4, h = blockIdx.y & 15;

    const uint32_t ksb = smem_u32(&ks[0][0][0]);
    const uint32_t vsb = smem_u32(&vs[0][0][0]);

    const int b_n = (lane & 7) + (lane >> 4) * 8;
    const int b_k = ((lane >> 3) & 1) * 8;
    const int lm_r = ((lane >> 3) & 1) * 8 + (lane & 7);
    const int lm_jofs = (lane >> 4);
    const int lrow0 = t >> 3, lch = t & 7;

    #pragma unroll 1
    for (int pass = 0; pass < 2; pass++) {
        const int qtile = pass == 0 ? (int)blockIdx.x : (NQT - 1 - (int)blockIdx.x);
        const int bq = qtile * 128;
        const int qg0 = bq + w * 16 + g;
        const int kend = qtile * 2 + 1;

        uint32_t aq[4][4];
        {
            const __half* q0p = qkv + ((size_t)(b * SEQ + qg0)) * (3 * DIM) + h * 64;
            const __half* q1p = q0p + (size_t)8 * (3 * DIM);
            const __half2 sc = __half2half2(__float2half(0.125f));
            #pragma unroll
            for (int kk = 0; kk < 4; kk++) {
                __half2 v0 = __hmul2(*(const __half2*)(q0p + kk * 16 + 2 * c), sc);
                __half2 v1 = __hmul2(*(const __half2*)(q1p + kk * 16 + 2 * c), sc);
                __half2 v2 = __hmul2(*(const __half2*)(q0p + kk * 16 + 2 * c + 8), sc);
                __half2 v3 = __hmul2(*(const __half2*)(q1p + kk * 16 + 2 * c + 8), sc);
                aq[kk][0] = *(uint32_t*)&v0; aq[kk][1] = *(uint32_t*)&v1;
                aq[kk][2] = *(uint32_t*)&v2; aq[kk][3] = *(uint32_t*)&v3;
            }
        }

        float o[8][4];
        #pragma unroll
        for (int i = 0; i < 8; i++) { o[i][0] = o[i][1] = o[i][2] = o[i][3] = 0.f; }
        float m0 = -1e30f, m1 = -1e30f, l0 = 0.f, l1 = 0.f;

        {
            #pragma unroll
            for (int j = 0; j < 2; j++) {
                int row = lrow0 + 32 * j;
                const __half* kp = qkv + ((size_t)(b * SEQ + row)) * (3 * DIM)
                                   + DIM + h * 64 + lch * 8;
                cpa16(ksb + row * (HSTRIDE * 2) + lch * 16, kp);
                cpa16(vsb + row * (HSTRIDE * 2) + lch * 16, kp + DIM);
            }
            asm volatile("cp.async.commit_group;");
        }

        #pragma unroll 1
        for (int kt = 0; kt <= kend; kt++) {
            const int bi = kt & 1;
            if (kt < kend) {
                const int ni = (kt + 1) & 1;
                #pragma unroll
                for (int j = 0; j < 2; j++) {
                    int row = lrow0 + 32 * j;
                    const __half* kp = qkv + ((size_t)(b * SEQ + (kt + 1) * 64 + row)) * (3 * DIM)
                                       + DIM + h * 64 + lch * 8;
                    cpa16(ksb + ni * KVB + row * (HSTRIDE * 2) + lch * 16, kp);
                    cpa16(vsb + ni * KVB + row * (HSTRIDE * 2) + lch * 16, kp + DIM);
                }
            }
            asm volatile("cp.async.commit_group; cp.async.wait_group 1;");
            __syncthreads();

            float sacc[8][4];
            #pragma unroll
            for (int i = 0; i < 8; i++) { sacc[i][0] = sacc[i][1] = sacc[i][2] = sacc[i][3] = 0.f; }
            const uint32_t kBase = ksb + bi * KVB + (b_n * HSTRIDE + b_k) * 2;
            #pragma unroll
            for (int kk = 0; kk < 4; kk++) {
                uint32_t kf[4][4];
                #pragma unroll
                for (int nt2 = 0; nt2 < 4; nt2++)
                    ldsm4(kf[nt2], kBase + nt2 * 16 * (HSTRIDE * 2) + kk * 32);
                #pragma unroll
                for (int nt = 0; nt < 8; nt++)
                    mma16(sacc[nt], aq[kk],
                          kf[nt >> 1][(nt & 1) * 2], kf[nt >> 1][(nt & 1) * 2 + 1]);
            }

            if (kt * 64 + 63 > bq + w * 16) {
                #pragma unroll
                for (int nt = 0; nt < 8; nt++) {
                    int colb = kt * 64 + nt * 8 + 2 * c;
                    if (colb     > qg0)     sacc[nt][0] = -1e30f;
                    if (colb + 1 > qg0)     sacc[nt][1] = -1e30f;
                    if (colb     > qg0 + 8) sacc[nt][2] = -1e30f;
                    if (colb + 1 > qg0 + 8) sacc[nt][3] = -1e30f;
                }
            }

            float mx0 = -1e30f, mx1 = -1e30f;
            #pragma unroll
            for (int nt = 0; nt < 8; nt++) {
                mx0 = fmaxf(mx0, fmaxf(sacc[nt][0], sacc[nt][1]));
                mx1 = fmaxf(mx1, fmaxf(sacc[nt][2], sacc[nt][3]));
            }
            mx0 = fmaxf(mx0, __shfl_xor_sync(0xFFFFFFFFu, mx0, 1));
            mx0 = fmaxf(mx0, __shfl_xor_sync(0xFFFFFFFFu, mx0, 2));
            mx1 = fmaxf(mx1, __shfl_xor_sync(0xFFFFFFFFu, mx1, 1));
            mx1 = fmaxf(mx1, __shfl_xor_sync(0xFFFFFFFFu, mx1, 2));
            float nm0 = fmaxf(m0, mx0), nm1 = fmaxf(m1, mx1);
            float al0 = __expf(m0 - nm0), al1 = __expf(m1 - nm1);
            m0 = nm0; m1 = nm1;

            float ls0 = 0.f, ls1 = 0.f;
            uint32_t pa[4][4];
            #pragma unroll
            for (int nt = 0; nt < 8; nt++) {
                float p0 = __expf(sacc[nt][0] - nm0);
                float p1 = __expf(sacc[nt][1] - nm0);
                float p2 = __expf(sacc[nt][2] - nm1);
                float p3 = __expf(sacc[nt][3] - nm1);
                ls0 += p0 + p1; ls1 += p2 + p3;
                const int kk = nt >> 1;
                if ((nt & 1) == 0) {
                    pa[kk][0] = packh2(p0, p1);
                    pa[kk][1] = packh2(p2, p3);
                } else {
                    pa[kk][2] = packh2(p0, p1);
                    pa[kk][3] = packh2(p2, p3);
                }
                o[nt][0] *= al0; o[nt][1] *= al0;
                o[nt][2] *= al1; o[nt][3] *= al1;
            }
            ls0 += __shfl_xor_sync(0xFFFFFFFFu, ls0, 1);
            ls0 += __shfl_xor_sync(0xFFFFFFFFu, ls0, 2);
            ls1 += __shfl_xor_sync(0xFFFFFFFFu, ls1, 1);
            ls1 += __shfl_xor_sync(0xFFFFFFFFu, ls1, 2);
            l0 = l0 * al0 + ls0;
            l1 = l1 * al1 + ls1;

            const uint32_t vBase = vsb + bi * KVB;
            #pragma unroll
            for (int kk = 0; kk < 4; kk++) {
                #pragma unroll
                for (int j = 0; j < 8; j += 2) {
                    uint32_t r0, r1, r2, r3;
                    uint32_t addr = vBase + (kk * 16 + lm_r) * (HSTRIDE * 2)
                                  + (j + lm_jofs) * 8 * 2;
                    asm volatile(
                        "ldmatrix.sync.aligned.m8n8.x4.trans.shared.b16 {%0,%1,%2,%3}, [%4];"
                        : "=r"(r0), "=r"(r1), "=r"(r2), "=r"(r3) : "r"(addr));
                    mma16(o[j],     pa[kk], r0, r1);
                    mma16(o[j + 1], pa[kk], r2, r3);
                }
            }
            __syncthreads();
        }

        float il0 = 1.0f / l0, il1 = 1.0f / l1;
        size_t o0 = ((size_t)(b * SEQ + qg0)) * DIM + h * 64;
        size_t o1 = o0 + (size_t)8 * DIM;
        #pragma unroll
        for (int nt = 0; nt < 8; nt++) {
            int cl = nt * 8 + 2 * c;
            *(__half2*)&out[o0 + cl] = __floats2half2_rn(o[nt][0] * il0, o[nt][1] * il0);
            *(__half2*)&out[o1 + cl] = __floats2half2_rn(o[nt][2] * il1, o[nt][3] * il1);
        }
    }
}

// ---------------- Launch -------------------------------------------------------
extern "C" void kernel_launch(void* const* d_in, const int* in_sizes, int n_in,
                              void* d_out, int out_size)
{
    const float* hidden    = (const float*)d_in[0];
    const float* w_attn    = (const float*)d_in[1];
    const float* b_attn    = (const float*)d_in[2];
    const float* w_proj    = (const float*)d_in[3];
    const float* b_proj    = (const float*)d_in[4];
    const float* w_fc      = (const float*)d_in[5];
    const float* b_fc      = (const float*)d_in[6];
    const float* w_fc_proj = (const float*)d_in[7];
    const float* b_fc_proj = (const float*)d_in[8];
    const float* ln1_w     = (const float*)d_in[9];
    const float* ln1_b     = (const float*)d_in[10];
    const float* ln2_w     = (const float*)d_in[11];
    const float* ln2_b     = (const float*)d_in[12];
    float* outp            = (float*)d_out;

    __half *px, *pqkv, *patt, *py, *pfc, *pwa, *pwp, *pwf, *pwfp;
    float *ph;
    cudaGetSymbolAddress((void**)&px,   g_x);
    cudaGetSymbolAddress((void**)&pqkv, g_qkv);
    cudaGetSymbolAddress((void**)&patt, g_att);
    cudaGetSymbolAddress((void**)&ph,   g_h);
    cudaGetSymbolAddress((void**)&py,   g_y);
    cudaGetSymbolAddress((void**)&pfc,  g_fc);
    cudaGetSymbolAddress((void**)&pwa,  g_waT);
    cudaGetSymbolAddress((void**)&pwp,  g_wpT);
    cudaGetSymbolAddress((void**)&pwf,  g_wfT);
    cudaGetSymbolAddress((void**)&pwfp, g_wfpT);

    cudaFuncSetAttribute(gemm_h<0, __half>, cudaFuncAttributeMaxDynamicSharedMemorySize, GEMM_SMEM);
    cudaFuncSetAttribute(gemm_h<1, __half>, cudaFuncAttributeMaxDynamicSharedMemorySize, GEMM_SMEM);
    cudaFuncSetAttribute(gemm_h<2, float>,  cudaFuncAttributeMaxDynamicSharedMemorySize, GEMM_SMEM);

    // merged weight convert+transpose: one launch for all 4 matrices
    wconv_all<<<WT_TOT, dim3(32, 8)>>>(w_attn, w_proj, w_fc, w_fc_proj,
                                       pwa, pwp, pwf, pwfp);

    ln_h<<<MROWS, 256>>>(hidden, ln1_w, ln1_b, px);

    gemm_h<0, __half><<<dim3(3 * DIM / 128, MROWS / 128), 256, GEMM_SMEM>>>(
        px, pwa, b_attn, nullptr, pqkv, MROWS, 3 * DIM, DIM);

    attn_h<<<dim3(SEQ / 256, BS_ * NH), 256>>>(pqkv, patt);

    gemm_h<2, float><<<dim3(DIM / 128, MROWS / 128), 256, GEMM_SMEM>>>(
        patt, pwp, b_proj, hidden, ph, MROWS, DIM, DIM);

    ln_h<<<MROWS, 256>>>(ph, ln2_w, ln2_b, py);

    gemm_h<1, __half><<<dim3(DFF / 128, MROWS / 128), 256, GEMM_SMEM>>>(
        py, pwf, b_fc, nullptr, pfc, MROWS, DFF, DIM);

    gemm_h<2, float><<<dim3(DIM / 128, MROWS / 128), 256, GEMM_SMEM>>>(
        pfc, pwfp, b_fc_proj, ph, outp, MROWS, DIM, DFF);
}